// round 15
// baseline (speedup 1.0000x reference)
#include <cuda_runtime.h>
#include <cstdint>

// Fixed dataset geometry: 512x512 grid mesh, batch 32.
#define W 512
#define H 512
#define NV (H * W)
#define FC (W * 3)          // 1536 float columns per grid row
#define FCG 12              // warp covers 128 float-cols; thread owns 4
#define RPW 32              // rows per warp chunk
#define CHUNKS (H / RPW)    // 16
#define WPB (FCG * CHUNKS)  // warps per batch = 192
#define BLOCK_THREADS 256
#define WARPS_PER_BLOCK (BLOCK_THREADS / 32)
#define SLOTB 576           // bytes per ring slot (544 data + pad)
#define NSLOT 8
#define MAX_BLOCKS 1024

__device__ float    g_parts[MAX_BLOCKS];
__device__ unsigned g_count = 0;

__device__ __forceinline__ uint32_t smem_u32(const void* p) {
    uint32_t a;
    asm("{ .reg .u64 t; cvta.to.shared.u64 t, %1; cvt.u32.u64 %0, t; }"
        : "=r"(a) : "l"(p));
    return a;
}

__device__ __forceinline__ void cp16(uint32_t dst, const void* src) {
    asm volatile("cp.async.cg.shared.global [%0], [%1], 16;" :: "r"(dst), "l"(src) : "memory");
}
__device__ __forceinline__ void cp_commit() {
    asm volatile("cp.async.commit_group;" ::: "memory");
}
__device__ __forceinline__ void cp_wait4() {
    asm volatile("cp.async.wait_group 4;" ::: "memory");
}

// Walk RPW rows. Rows stream through a warp-private SMEM ring via cp.async;
// each thread reads its 12-float window [f0-4 .. f0+7] with 3 LDS.128.
// EDGE = warp's column group touches the grid's left/right boundary.
template<bool EDGE>
__device__ __forceinline__ float walk(const float* __restrict__ vb,
                                      uint32_t ringW, int cg, int lane, int r0)
{
    int base = cg * 128;                 // warp's first float column
    int f0   = base + lane * 4;          // thread's first float column

    // Global source columns (16B aligned). Clamped for boundary warps; the
    // resulting garbage taps are zeroed by mL/mR masks.
    int colMain = base + lane * 4;
    int colHL   = (cg > 0)       ? base - 4   : 0;
    int colHR   = (cg < FCG - 1) ? base + 128 : FC - 4;

    // Edge-only per-column masks / coefficients (f = f0+t).
    float mL[4], mR[4], cMid[4], cTop[4], cBot[4];
    if (EDGE) {
#pragma unroll
        for (int t = 0; t < 4; t++) {
            int f = f0 + t;
            mL[t] = (f >= 3)     ? 1.0f : 0.0f;
            mR[t] = (f < FC - 3) ? 1.0f : 0.0f;
            cMid[t] = -1.0f / (2.0f + 2.0f * (mL[t] + mR[t]));
            cTop[t] = -1.0f / (1.0f + 2.0f * mL[t] + mR[t]);
            cBot[t] = -1.0f / (1.0f + mL[t] + 2.0f * mR[t]);
        }
    }

    // Issue one row into ring slot s. Slot layout (floats):
    // [0..3] halo-left (cols base-4..base-1), [4..131] main, [132..135] halo-right.
    auto issue_row = [&](int r, int s) {
        if (r > H - 1) r = H - 1;
        const float* row = vb + (size_t)r * FC;
        uint32_t slot = ringW + (uint32_t)(s * SLOTB);
        cp16(slot + 16u + (uint32_t)(lane * 16), row + colMain);
        if (lane == 0)  cp16(slot,        row + colHL);
        if (lane == 31) cp16(slot + 528u, row + colHR);
        cp_commit();
    };

    // Rolling windows: A = row i-1, B = row i, C = row i+1. w[k] = col f0-4+k.
    float A[12], Bw[12], Cw[12];
    float acc = 0.0f;

    auto load_win = [&](int s, float w[12]) {
        uint32_t a = ringW + (uint32_t)(s * SLOTB) + (uint32_t)(lane * 16);
        float4 v0, v1, v2;
        asm volatile("ld.shared.v4.f32 {%0,%1,%2,%3}, [%4];"
                     : "=f"(v0.x), "=f"(v0.y), "=f"(v0.z), "=f"(v0.w) : "r"(a));
        asm volatile("ld.shared.v4.f32 {%0,%1,%2,%3}, [%4];"
                     : "=f"(v1.x), "=f"(v1.y), "=f"(v1.z), "=f"(v1.w) : "r"(a + 16u));
        asm volatile("ld.shared.v4.f32 {%0,%1,%2,%3}, [%4];"
                     : "=f"(v2.x), "=f"(v2.y), "=f"(v2.z), "=f"(v2.w) : "r"(a + 32u));
        w[0] = v0.x; w[1]  = v0.y; w[2]  = v0.z; w[3]  = v0.w;
        w[4] = v1.x; w[5]  = v1.y; w[6]  = v1.z; w[7]  = v1.w;
        w[8] = v2.x; w[9]  = v2.y; w[10] = v2.z; w[11] = v2.w;
    };

    // phase: 0 = top row (no up-neighbors), 1 = interior, 2 = bottom row.
    auto compute = [&](int phase) {
        float mU = (phase == 0) ? 0.0f : 1.0f;
        float mD = (phase == 2) ? 0.0f : 1.0f;
#pragma unroll
        for (int t = 0; t < 4; t++) {
            float bm = Bw[1 + t], bp = Bw[7 + t];
            float av = A[4 + t],  ap = A[7 + t];
            float cm = Cw[1 + t], cv = Cw[4 + t];
            float bv = Bw[4 + t];
            float Lv;
            if (EDGE) {
                float sl = fmaf(mD, cm, bm);
                float sr = fmaf(mU, ap, bp);
                float s  = fmaf(mU, av, mD * cv);
                s = fmaf(mL[t], sl, s);
                s = fmaf(mR[t], sr, s);
                float coef = (phase == 0) ? cTop[t] : ((phase == 2) ? cBot[t] : cMid[t]);
                Lv = fmaf(coef, s, bv);
            } else {
                float s, coef;
                if (phase == 0) {        // left, right, down, down-left
                    s = (bm + cm) + (bp + cv);
                    coef = -(1.0f / 4.0f);
                } else if (phase == 2) { // left, right, up, up-right
                    s = (bm + bp) + (av + ap);
                    coef = -(1.0f / 4.0f);
                } else {                 // 6 neighbors
                    s = (bm + cm) + ((bp + ap) + (av + cv));
                    coef = -(1.0f / 6.0f);
                }
                Lv = fmaf(coef, s, bv);
            }
            acc = fmaf(Lv, Lv, acc);
        }
    };

    auto rotate = [&]() {
#pragma unroll
        for (int t = 0; t < 12; t++) { A[t] = Bw[t]; Bw[t] = Cw[t]; }
    };

    // ---- prologue: issue rows r0-1 .. r0+4 into slots 0..5 ----
#pragma unroll
    for (int s = 0; s < 6; s++) {
        int r = r0 - 1 + s;
        if (r < 0) r = 0;
        issue_row(r, s);
    }
    cp_wait4();                        // rows r0-1, r0 complete
    __syncwarp();
    load_win(0, A);                    // row r0-1 (clamped; masked for top chunk)
    load_win(1, Bw);                   // row r0

    // One pipeline step: i = r0+k. Issues row i+5, waits row i+1, computes row i.
    auto step = [&](int k, int phase) {
        issue_row(r0 + k + 5, (k + 6) & (NSLOT - 1));
        cp_wait4();                    // row i+1 (slot k+2) complete
        __syncwarp();
        load_win((k + 2) & (NSLOT - 1), Cw);
        compute(phase);
        rotate();
    };

    int k = 0;
    if (r0 == 0) { step(0, 0); k = 1; }          // peel top boundary row
    bool hasBot = (r0 + RPW == H);
    int kmain = hasBot ? RPW - 1 : RPW;
#pragma unroll 4
    for (; k < kmain; k++) step(k, 1);
    if (hasBot) step(RPW - 1, 2);                // peel bottom row (C masked)

    return acc;
}

__global__ __launch_bounds__(BLOCK_THREADS, 3)
void lap_kernel(const float* __restrict__ verts, float* __restrict__ out, float scale)
{
    __shared__ __align__(128) unsigned char ring[WARPS_PER_BLOCK * NSLOT * SLOTB];
    __shared__ float warp_sums[WARPS_PER_BLOCK];

    const unsigned FULL = 0xFFFFFFFFu;
    int lane = threadIdx.x & 31;
    int wid  = threadIdx.x >> 5;
    int gw   = (blockIdx.x * BLOCK_THREADS + threadIdx.x) >> 5;

    int bb  = gw / WPB;
    int rem = gw - bb * WPB;
    int cg  = rem % FCG;
    int rc  = rem / FCG;
    int r0  = rc * RPW;

    const float* vb = verts + (size_t)bb * NV * 3;
    uint32_t ringW = smem_u32(ring) + (uint32_t)(wid * NSLOT * SLOTB);
    bool edge = (cg == 0) || (cg == FCG - 1);

    float acc = edge ? walk<true >(vb, ringW, cg, lane, r0)
                     : walk<false>(vb, ringW, cg, lane, r0);

    // drain any outstanding async copies before SMEM reuse / exit
    asm volatile("cp.async.wait_all;" ::: "memory");
    __syncwarp();

    // ---- reduce: warp -> block -> device-wide last-block-done ----
#pragma unroll
    for (int off = 16; off > 0; off >>= 1)
        acc += __shfl_xor_sync(FULL, acc, off);

    if (lane == 0) warp_sums[wid] = acc;
    __syncthreads();

    __shared__ bool isLast;
    if (threadIdx.x == 0) {
        float bs = 0.0f;
#pragma unroll
        for (int k = 0; k < WARPS_PER_BLOCK; k++) bs += warp_sums[k];
        g_parts[blockIdx.x] = bs;
        __threadfence();
        unsigned p = atomicAdd(&g_count, 1u);
        isLast = (p == gridDim.x - 1);
    }
    __syncthreads();

    if (isLast) {
        float s = 0.0f;
        for (int idx = threadIdx.x; idx < (int)gridDim.x; idx += BLOCK_THREADS)
            s += g_parts[idx];
#pragma unroll
        for (int off = 16; off > 0; off >>= 1)
            s += __shfl_xor_sync(FULL, s, off);
        if (lane == 0) warp_sums[wid] = s;
        __syncthreads();
        if (threadIdx.x == 0) {
            float tot = 0.0f;
#pragma unroll
            for (int k = 0; k < WARPS_PER_BLOCK; k++) tot += warp_sums[k];
            out[0] = tot * scale;
            g_count = 0;                          // reset for next launch
        }
    }
}

extern "C" void kernel_launch(void* const* d_in, const int* in_sizes, int n_in,
                              void* d_out, int out_size) {
    const float* verts = (const float*)d_in[0];
    int B = in_sizes[0] / (NV * 3);

    int total_warps  = B * WPB;                         // 6144
    int total_blocks = total_warps / WARPS_PER_BLOCK;   // 768
    float scale = 1.0f / ((float)B * (float)NV);
    lap_kernel<<<total_blocks, BLOCK_THREADS>>>(verts, (float*)d_out, scale);
}

// round 16
// speedup vs baseline: 1.0338x; 1.0338x over previous
#include <cuda_runtime.h>
#include <cstdint>

// Fixed dataset geometry: 512x512 grid mesh, batch 32.
#define W 512
#define H 512
#define NV (H * W)
#define FC (W * 3)          // 1536 float columns per grid row
#define FCG 12              // warp covers 128 float-cols; thread owns 4
#define RPW 32              // rows per warp chunk
#define CHUNKS (H / RPW)    // 16
#define WPB (FCG * CHUNKS)  // warps per batch = 192
#define BLOCK_THREADS 256
#define WARPS_PER_BLOCK (BLOCK_THREADS / 32)
#define SLOTB 576           // bytes per ring slot (544 data + pad)
#define NSLOT 8

__device__ float    g_loss  = 0.0f;
__device__ unsigned g_count = 0;

__device__ __forceinline__ uint32_t smem_u32(const void* p) {
    uint32_t a;
    asm("{ .reg .u64 t; cvta.to.shared.u64 t, %1; cvt.u32.u64 %0, t; }"
        : "=r"(a) : "l"(p));
    return a;
}

__device__ __forceinline__ void cp16(uint32_t dst, const void* src) {
    asm volatile("cp.async.cg.shared.global [%0], [%1], 16;" :: "r"(dst), "l"(src) : "memory");
}
__device__ __forceinline__ void cp_commit() {
    asm volatile("cp.async.commit_group;" ::: "memory");
}
__device__ __forceinline__ void cp_wait4() {
    asm volatile("cp.async.wait_group 4;" ::: "memory");
}

// Walk RPW rows. Rows stream through a warp-private SMEM ring via cp.async;
// each thread reads its 12-float window [f0-4 .. f0+7] with 3 LDS.128.
// EDGE = warp's column group touches the grid's left/right boundary.
template<bool EDGE>
__device__ __forceinline__ float walk(const float* __restrict__ vb,
                                      uint32_t ringW, int cg, int lane, int r0)
{
    int base = cg * 128;                 // warp's first float column
    int f0   = base + lane * 4;          // thread's first float column

    // Global source columns (16B aligned). Clamped for boundary warps; the
    // resulting garbage taps are zeroed by mL/mR masks.
    int colMain = base + lane * 4;
    int colHL   = (cg > 0)       ? base - 4   : 0;
    int colHR   = (cg < FCG - 1) ? base + 128 : FC - 4;

    // Edge-only per-column masks / coefficients (f = f0+t).
    float mL[4], mR[4], cMid[4], cTop[4], cBot[4];
    if (EDGE) {
#pragma unroll
        for (int t = 0; t < 4; t++) {
            int f = f0 + t;
            mL[t] = (f >= 3)     ? 1.0f : 0.0f;
            mR[t] = (f < FC - 3) ? 1.0f : 0.0f;
            cMid[t] = -1.0f / (2.0f + 2.0f * (mL[t] + mR[t]));
            cTop[t] = -1.0f / (1.0f + 2.0f * mL[t] + mR[t]);
            cBot[t] = -1.0f / (1.0f + mL[t] + 2.0f * mR[t]);
        }
    }

    // Issue one row into ring slot s. Slot layout (floats):
    // [0..3] halo-left (cols base-4..base-1), [4..131] main, [132..135] halo-right.
    auto issue_row = [&](int r, int s) {
        if (r > H - 1) r = H - 1;
        const float* row = vb + (size_t)r * FC;
        uint32_t slot = ringW + (uint32_t)(s * SLOTB);
        cp16(slot + 16u + (uint32_t)(lane * 16), row + colMain);
        if (lane == 0)  cp16(slot,        row + colHL);
        if (lane == 31) cp16(slot + 528u, row + colHR);
        cp_commit();
    };

    // Rolling windows: A = row i-1, B = row i, C = row i+1. w[k] = col f0-4+k.
    float A[12], Bw[12], Cw[12];
    float acc = 0.0f;

    auto load_win = [&](int s, float w[12]) {
        uint32_t a = ringW + (uint32_t)(s * SLOTB) + (uint32_t)(lane * 16);
        float4 v0, v1, v2;
        asm volatile("ld.shared.v4.f32 {%0,%1,%2,%3}, [%4];"
                     : "=f"(v0.x), "=f"(v0.y), "=f"(v0.z), "=f"(v0.w) : "r"(a));
        asm volatile("ld.shared.v4.f32 {%0,%1,%2,%3}, [%4];"
                     : "=f"(v1.x), "=f"(v1.y), "=f"(v1.z), "=f"(v1.w) : "r"(a + 16u));
        asm volatile("ld.shared.v4.f32 {%0,%1,%2,%3}, [%4];"
                     : "=f"(v2.x), "=f"(v2.y), "=f"(v2.z), "=f"(v2.w) : "r"(a + 32u));
        w[0] = v0.x; w[1]  = v0.y; w[2]  = v0.z; w[3]  = v0.w;
        w[4] = v1.x; w[5]  = v1.y; w[6]  = v1.z; w[7]  = v1.w;
        w[8] = v2.x; w[9]  = v2.y; w[10] = v2.z; w[11] = v2.w;
    };

    // phase: 0 = top row (no up-neighbors), 1 = interior, 2 = bottom row.
    auto compute = [&](int phase) {
        float mU = (phase == 0) ? 0.0f : 1.0f;
        float mD = (phase == 2) ? 0.0f : 1.0f;
#pragma unroll
        for (int t = 0; t < 4; t++) {
            float bm = Bw[1 + t], bp = Bw[7 + t];
            float av = A[4 + t],  ap = A[7 + t];
            float cm = Cw[1 + t], cv = Cw[4 + t];
            float bv = Bw[4 + t];
            float Lv;
            if (EDGE) {
                float sl = fmaf(mD, cm, bm);
                float sr = fmaf(mU, ap, bp);
                float s  = fmaf(mU, av, mD * cv);
                s = fmaf(mL[t], sl, s);
                s = fmaf(mR[t], sr, s);
                float coef = (phase == 0) ? cTop[t] : ((phase == 2) ? cBot[t] : cMid[t]);
                Lv = fmaf(coef, s, bv);
            } else {
                float s, coef;
                if (phase == 0) {        // left, right, down, down-left
                    s = (bm + cm) + (bp + cv);
                    coef = -(1.0f / 4.0f);
                } else if (phase == 2) { // left, right, up, up-right
                    s = (bm + bp) + (av + ap);
                    coef = -(1.0f / 4.0f);
                } else {                 // 6 neighbors
                    s = (bm + cm) + ((bp + ap) + (av + cv));
                    coef = -(1.0f / 6.0f);
                }
                Lv = fmaf(coef, s, bv);
            }
            acc = fmaf(Lv, Lv, acc);
        }
    };

    auto rotate = [&]() {
#pragma unroll
        for (int t = 0; t < 12; t++) { A[t] = Bw[t]; Bw[t] = Cw[t]; }
    };

    // ---- prologue: issue rows r0-1 .. r0+4 into slots 0..5 ----
#pragma unroll
    for (int s = 0; s < 6; s++) {
        int r = r0 - 1 + s;
        if (r < 0) r = 0;
        issue_row(r, s);
    }
    cp_wait4();                        // rows r0-1, r0 complete
    __syncwarp();
    load_win(0, A);                    // row r0-1 (clamped; masked for top chunk)
    load_win(1, Bw);                   // row r0

    // One pipeline step: i = r0+k. Issues row i+5, waits row i+1, computes row i.
    auto step = [&](int k, int phase) {
        issue_row(r0 + k + 5, (k + 6) & (NSLOT - 1));
        cp_wait4();                    // row i+1 (slot k+2) complete
        __syncwarp();
        load_win((k + 2) & (NSLOT - 1), Cw);
        compute(phase);
        rotate();
    };

    int k = 0;
    if (r0 == 0) { step(0, 0); k = 1; }          // peel top boundary row
    bool hasBot = (r0 + RPW == H);
    int kmain = hasBot ? RPW - 1 : RPW;
#pragma unroll 4
    for (; k < kmain; k++) step(k, 1);
    if (hasBot) step(RPW - 1, 2);                // peel bottom row (C masked)

    return acc;
}

__global__ __launch_bounds__(BLOCK_THREADS, 3)
void lap_kernel(const float* __restrict__ verts, float* __restrict__ out, float scale)
{
    __shared__ __align__(128) unsigned char ring[WARPS_PER_BLOCK * NSLOT * SLOTB];
    __shared__ float warp_sums[WARPS_PER_BLOCK];

    const unsigned FULL = 0xFFFFFFFFu;
    int lane = threadIdx.x & 31;
    int wid  = threadIdx.x >> 5;
    int gw   = (blockIdx.x * BLOCK_THREADS + threadIdx.x) >> 5;

    int bb  = gw / WPB;
    int rem = gw - bb * WPB;
    int cg  = rem % FCG;
    int rc  = rem / FCG;
    int r0  = rc * RPW;

    const float* vb = verts + (size_t)bb * NV * 3;
    uint32_t ringW = smem_u32(ring) + (uint32_t)(wid * NSLOT * SLOTB);
    bool edge = (cg == 0) || (cg == FCG - 1);

    float acc = edge ? walk<true >(vb, ringW, cg, lane, r0)
                     : walk<false>(vb, ringW, cg, lane, r0);

    // drain any outstanding async copies before SMEM reuse / exit
    asm volatile("cp.async.wait_all;" ::: "memory");
    __syncwarp();

    // ---- reduce: warp -> block -> one global atomic + O(1) finalize ----
#pragma unroll
    for (int off = 16; off > 0; off >>= 1)
        acc += __shfl_xor_sync(FULL, acc, off);

    if (lane == 0) warp_sums[wid] = acc;
    __syncthreads();

    if (threadIdx.x == 0) {
        float bs = 0.0f;
#pragma unroll
        for (int k = 0; k < WARPS_PER_BLOCK; k++) bs += warp_sums[k];
        atomicAdd(&g_loss, bs);                   // same cheap tail as R11
        __threadfence();
        unsigned p = atomicAdd(&g_count, 1u);
        if (p == gridDim.x - 1) {                 // last block: O(1) finalize
            __threadfence();
            float tot = g_loss;
            out[0] = tot * scale;
            g_loss  = 0.0f;                       // reset for next graph replay
            g_count = 0;
        }
    }
}

extern "C" void kernel_launch(void* const* d_in, const int* in_sizes, int n_in,
                              void* d_out, int out_size) {
    const float* verts = (const float*)d_in[0];
    int B = in_sizes[0] / (NV * 3);

    int total_warps  = B * WPB;                         // 6144
    int total_blocks = total_warps / WARPS_PER_BLOCK;   // 768
    float scale = 1.0f / ((float)B * (float)NV);
    lap_kernel<<<total_blocks, BLOCK_THREADS>>>(verts, (float*)d_out, scale);
}

// round 17
// speedup vs baseline: 1.1064x; 1.0702x over previous
#include <cuda_runtime.h>

// Fixed dataset geometry: 512x512 grid mesh, batch 32.
#define W 512
#define H 512
#define NV (H * W)
#define FC (W * 3)          // 1536 float columns per grid row
#define FCG 12              // warp covers 128 float-cols -> 12 groups
#define RPW 32              // rows per warp
#define CHUNKS (H / RPW)    // 16
#define WPB (FCG * CHUNKS)  // warps per batch = 192
#define BLOCK_THREADS 256
#define WARPS_PER_BLOCK (BLOCK_THREADS / 32)

__device__ float    g_loss  = 0.0f;
__device__ unsigned g_count = 0;

__global__ __launch_bounds__(BLOCK_THREADS)
void lap_kernel(const float* __restrict__ verts, float* __restrict__ out, float scale)
{
    const unsigned FULL = 0xFFFFFFFFu;
    int lane = threadIdx.x & 31;
    int gw   = (blockIdx.x * BLOCK_THREADS + threadIdx.x) >> 5;

    int bb  = gw / WPB;
    int rem = gw - bb * WPB;
    int cg  = rem % FCG;
    int rc  = rem / FCG;
    int j   = cg * 32 + lane;            // (unused name kept for parity)
    (void)j;
    int r0  = rc * RPW;

    const float* vb = verts + (size_t)bb * NV * 3;
    int fidx  = cg * 32 + lane;          // float4 index within a grid row
    int fbase = cg * 128 + lane * 4;     // first float column owned by this lane
    bool doL = (lane == 0)  && (cg > 0);
    bool doR = (lane == 31) && (cg < FCG - 1);

    // Per-float-column boundary masks and interior coefficient (constants).
    float mL[4], mR[4], cMid[4];
#pragma unroll
    for (int t = 0; t < 4; t++) {
        int f = fbase + t;
        mL[t] = (f >= 3)      ? 1.0f : 0.0f;
        mR[t] = (f < FC - 3)  ? 1.0f : 0.0f;
        cMid[t] = -1.0f / (2.0f + 2.0f * (mL[t] + mR[t]));
    }

    // Row state: a = i-1, b = i, c = i+1. *m3 / *p3 = values shifted by -3/+3 floats.
    float4 a4, b4, c4;
    float ap3[3], bm3[3], bp3[3], cm3[3], cp3[3];

    auto load_row = [&](int r, float4& v4, float m3[3], float p3[3]) {
        const float4* rowp = (const float4*)(vb + (size_t)r * FC);
        v4 = __ldg(rowp + fidx);
        float4 hl = make_float4(0.f, 0.f, 0.f, 0.f);
        float4 hr = make_float4(0.f, 0.f, 0.f, 0.f);
        if (doL) hl = __ldg(rowp + fidx - 1);
        if (doR) hr = __ldg(rowp + fidx + 1);
        float uy = __shfl_up_sync(FULL, v4.y, 1);
        float uz = __shfl_up_sync(FULL, v4.z, 1);
        float uw = __shfl_up_sync(FULL, v4.w, 1);
        float dx = __shfl_down_sync(FULL, v4.x, 1);
        float dy = __shfl_down_sync(FULL, v4.y, 1);
        float dz = __shfl_down_sync(FULL, v4.z, 1);
        m3[0] = (lane == 0)  ? hl.y : uy;
        m3[1] = (lane == 0)  ? hl.z : uz;
        m3[2] = (lane == 0)  ? hl.w : uw;
        p3[0] = (lane == 31) ? hr.x : dx;
        p3[1] = (lane == 31) ? hr.y : dy;
        p3[2] = (lane == 31) ? hr.z : dz;
    };

    float acc = 0.0f;

    auto compute = [&](const float coef[4], float mU, float mD) {
        float bm[4] = {bm3[0], bm3[1], bm3[2], b4.x};
        float bp[4] = {b4.w,  bp3[0], bp3[1], bp3[2]};
        float ap[4] = {a4.w,  ap3[0], ap3[1], ap3[2]};
        float cm[4] = {cm3[0], cm3[1], cm3[2], c4.x};
        float av[4] = {a4.x, a4.y, a4.z, a4.w};
        float cv[4] = {c4.x, c4.y, c4.z, c4.w};
        float bv[4] = {b4.x, b4.y, b4.z, b4.w};
#pragma unroll
        for (int t = 0; t < 4; t++) {
            float sl = fmaf(mD, cm[t], bm[t]);     // left col:  b[f-3] + mD*c[f-3]
            float sr = fmaf(mU, ap[t], bp[t]);     // right col: b[f+3] + mU*a[f+3]
            float s  = fmaf(mU, av[t], mD * cv[t]);
            s = fmaf(mL[t], sl, s);
            s = fmaf(mR[t], sr, s);
            float Lv = fmaf(coef[t], s, bv[t]);
            acc = fmaf(Lv, Lv, acc);
        }
    };

    auto rotate = [&]() {
        a4 = b4; b4 = c4;
#pragma unroll
        for (int t = 0; t < 3; t++) { ap3[t] = bp3[t]; bm3[t] = cm3[t]; bp3[t] = cp3[t]; }
    };

    // ---- preload rows r0-1 (a) and r0 (b) ----
    {
        int rm = (r0 > 0) ? r0 - 1 : 0;      // masked by mU on the top row
        float dm[3];
        load_row(rm, a4, dm, ap3);
        load_row(r0, b4, bm3, bp3);
    }

    int i    = r0;
    int iend = r0 + RPW;

    if (r0 == 0) {                            // peel top boundary row
        float cTop[4];
#pragma unroll
        for (int t = 0; t < 4; t++) cTop[t] = -1.0f / (1.0f + 2.0f * mL[t] + mR[t]);
        load_row(1, c4, cm3, cp3);
        compute(cTop, 0.0f, 1.0f);
        rotate();
        i = 1;
    }

    int mainEnd = (iend == H) ? H - 1 : iend;
#pragma unroll 4
    for (; i < mainEnd; i++) {
        load_row(i + 1, c4, cm3, cp3);
        compute(cMid, 1.0f, 1.0f);
        rotate();
    }

    if (iend == H) {                          // peel bottom boundary row
        float cBot[4];
#pragma unroll
        for (int t = 0; t < 4; t++) cBot[t] = -1.0f / (1.0f + mL[t] + 2.0f * mR[t]);
        // c-state is stale (masked by mD = 0)
        compute(cBot, 1.0f, 0.0f);
    }

    // ---- reduce: warp -> block -> one global atomic + O(1) finalize ----
#pragma unroll
    for (int off = 16; off > 0; off >>= 1)
        acc += __shfl_xor_sync(FULL, acc, off);

    __shared__ float warp_sums[WARPS_PER_BLOCK];
    int wid = threadIdx.x >> 5;
    if (lane == 0) warp_sums[wid] = acc;
    __syncthreads();

    if (threadIdx.x == 0) {
        float bs = 0.0f;
#pragma unroll
        for (int k = 0; k < WARPS_PER_BLOCK; k++) bs += warp_sums[k];
        atomicAdd(&g_loss, bs);
        __threadfence();
        unsigned p = atomicAdd(&g_count, 1u);
        if (p == gridDim.x - 1) {             // last block: O(1) finalize
            __threadfence();
            out[0] = g_loss * scale;
            g_loss  = 0.0f;                   // reset for next graph replay
            g_count = 0;
        }
    }
}

extern "C" void kernel_launch(void* const* d_in, const int* in_sizes, int n_in,
                              void* d_out, int out_size) {
    const float* verts = (const float*)d_in[0];
    int B = in_sizes[0] / (NV * 3);

    int total_warps  = B * WPB;
    int total_blocks = total_warps / WARPS_PER_BLOCK;   // 768
    float scale = 1.0f / ((float)B * (float)NV);
    lap_kernel<<<total_blocks, BLOCK_THREADS>>>(verts, (float*)d_out, scale);
}